// round 2
// baseline (speedup 1.0000x reference)
#include <cuda_runtime.h>
#include <cstdint>

#define N_TOK 2048
#define DIM   32
#define RFEAT 64
#define HDIM  128
#define TJ    64

// ---------- scratch (device globals; no allocation allowed) ----------
__device__ __align__(16) float g_Q[N_TOK * DIM];
__device__ __align__(16) float g_Kp[N_TOK * DIM];    // K * (log2e / sqrt(d))
__device__ __align__(16) float g_V[N_TOK * DIM];
__device__ __align__(16) float g_phiQ[N_TOK * RFEAT];
__device__ __align__(16) float g_phiK[N_TOK * RFEAT];
__device__ __align__(16) float g_M[RFEAT * DIM];     // phi_K^T @ V
__device__ __align__(16) float g_attn[N_TOK * DIM];  // attention output after Wo+bo

__device__ __forceinline__ float fast_ex2(float x) {
    float y;
    asm("ex2.approx.ftz.f32 %0, %1;" : "=f"(y) : "f"(x));
    return y;
}

// Warp-wide sum, result broadcast to all lanes. (No f32 redux on sm_103.)
__device__ __forceinline__ float warp_sum(float v) {
    v += __shfl_xor_sync(0xffffffffu, v, 16);
    v += __shfl_xor_sync(0xffffffffu, v, 8);
    v += __shfl_xor_sync(0xffffffffu, v, 4);
    v += __shfl_xor_sync(0xffffffffu, v, 2);
    v += __shfl_xor_sync(0xffffffffu, v, 1);
    return v;
}

// ---------------------------------------------------------------------
// K1: per-row QKV projection, row norms, random features phi_Q/phi_K.
// 2048 threads, 1 row each.
// ---------------------------------------------------------------------
__global__ void k1_proj(const float* __restrict__ Z,
                        const float* __restrict__ Wq, const float* __restrict__ bq,
                        const float* __restrict__ Wk, const float* __restrict__ bk,
                        const float* __restrict__ Wv, const float* __restrict__ bv,
                        const float* __restrict__ omega)
{
    __shared__ float sW[3][DIM * DIM];
    __shared__ float sB[3][DIM];
    __shared__ float sOm[DIM * RFEAT];

    int tid = threadIdx.x;
    for (int idx = tid; idx < DIM * DIM; idx += 256) {
        sW[0][idx] = Wq[idx]; sW[1][idx] = Wk[idx]; sW[2][idx] = Wv[idx];
    }
    for (int idx = tid; idx < DIM * RFEAT; idx += 256) sOm[idx] = omega[idx];
    if (tid < DIM) { sB[0][tid] = bq[tid]; sB[1][tid] = bk[tid]; sB[2][tid] = bv[tid]; }
    __syncthreads();

    int i = blockIdx.x * 256 + tid;

    float z[DIM];
    const float4* z4 = reinterpret_cast<const float4*>(Z + i * DIM);
    #pragma unroll
    for (int k4 = 0; k4 < DIM / 4; k4++) {
        float4 t = z4[k4];
        z[k4 * 4 + 0] = t.x; z[k4 * 4 + 1] = t.y; z[k4 * 4 + 2] = t.z; z[k4 * 4 + 3] = t.w;
    }

    const float L2E    = 1.4426950408889634f;
    const float KSCALE = (float)(1.4426950408889634 / 5.6568542494923806); // log2e/sqrt(32)

    #pragma unroll 1
    for (int p = 0; p < 3; p++) {
        float a[DIM];
        const float* W = sW[p];
        #pragma unroll
        for (int j = 0; j < DIM; j++) {
            float s = sB[p][j];
            #pragma unroll
            for (int k = 0; k < DIM; k++) s = fmaf(z[k], W[k * DIM + j], s);
            a[j] = s;
        }
        // store raw projection (scaled for K)
        {
            float4* dst4 = reinterpret_cast<float4*>(
                (p == 0 ? g_Q : (p == 1 ? g_Kp : g_V)) + i * DIM);
            float sc = (p == 1) ? KSCALE : 1.0f;
            #pragma unroll
            for (int j4 = 0; j4 < DIM / 4; j4++) {
                float4 t;
                t.x = a[j4 * 4 + 0] * sc; t.y = a[j4 * 4 + 1] * sc;
                t.z = a[j4 * 4 + 2] * sc; t.w = a[j4 * 4 + 3] * sc;
                dst4[j4] = t;
            }
        }
        if (p < 2) {
            float ss = 0.f;
            #pragma unroll
            for (int k = 0; k < DIM; k++) ss = fmaf(a[k], a[k], ss);
            float inv = 1.f / fmaxf(sqrtf(ss), 1e-6f);
            #pragma unroll
            for (int k = 0; k < DIM; k++) a[k] *= inv;

            float4* dst4 = reinterpret_cast<float4*>((p == 0 ? g_phiQ : g_phiK) + i * RFEAT);
            #pragma unroll 1
            for (int r4 = 0; r4 < RFEAT / 4; r4++) {
                float4 t;
                float* tp = &t.x;
                #pragma unroll
                for (int u = 0; u < 4; u++) {
                    int r = r4 * 4 + u;
                    float dr = 0.f;
                    #pragma unroll
                    for (int k = 0; k < DIM; k++) dr = fmaf(a[k], sOm[k * RFEAT + r], dr);
                    tp[u] = fast_ex2(dr * L2E) * 0.125f; // exp(dr)/sqrt(r), r=64
                }
                dst4[r4] = t;
            }
        }
    }
}

// ---------------------------------------------------------------------
// K2: M = phi_K^T @ V   [64 x 32]. One block per r.
// ---------------------------------------------------------------------
__global__ void k2_kv()
{
    int r = blockIdx.x;
    int tid = threadIdx.x, lane = tid & 31, w = tid >> 5;

    float acc[DIM];
    #pragma unroll
    for (int c = 0; c < DIM; c++) acc[c] = 0.f;

    for (int n = tid; n < N_TOK; n += 256) {
        float pk = g_phiK[n * RFEAT + r];
        const float4* v4 = reinterpret_cast<const float4*>(g_V + n * DIM);
        #pragma unroll
        for (int c4 = 0; c4 < DIM / 4; c4++) {
            float4 t = v4[c4];
            acc[c4 * 4 + 0] = fmaf(pk, t.x, acc[c4 * 4 + 0]);
            acc[c4 * 4 + 1] = fmaf(pk, t.y, acc[c4 * 4 + 1]);
            acc[c4 * 4 + 2] = fmaf(pk, t.z, acc[c4 * 4 + 2]);
            acc[c4 * 4 + 3] = fmaf(pk, t.w, acc[c4 * 4 + 3]);
        }
    }

    __shared__ float sm[8][DIM];
    float mine = 0.f;
    #pragma unroll
    for (int c = 0; c < DIM; c++) {
        float s = warp_sum(acc[c]);
        if (lane == c) mine = s;
    }
    sm[w][lane] = mine;
    __syncthreads();
    if (tid < DIM) {
        float t = 0.f;
        #pragma unroll
        for (int ww = 0; ww < 8; ww++) t += sm[ww][tid];
        g_M[r * DIM + tid] = t;
    }
}

// ---------------------------------------------------------------------
// K3: main attention. One warp per row, lanes over k/column dim.
// Per pair: exp-sum and phi-dot folded into ONE lane-partial, one reduction.
// ---------------------------------------------------------------------
__global__ void k3_attn(const int* __restrict__ mask,
                        const float* __restrict__ Wo, const float* __restrict__ bo)
{
    __shared__ float sKp[TJ * DIM];      // 8KB
    __shared__ float sV [TJ * DIM];      // 8KB
    __shared__ float sPK[TJ * RFEAT];    // 16KB
    __shared__ float sM [RFEAT * DIM];   // 8KB
    __shared__ float sWo[DIM * DIM];     // 4KB
    __shared__ float sBo[DIM];
    __shared__ float sA[8][DIM];         // 1KB

    int tid = threadIdx.x, lane = tid & 31, w = tid >> 5;

    for (int idx = tid; idx < RFEAT * DIM; idx += 256) sM[idx] = g_M[idx];
    for (int idx = tid; idx < DIM * DIM; idx += 256) sWo[idx] = Wo[idx];
    if (tid < DIM) sBo[tid] = bo[tid];

    int i = blockIdx.x * 8 + w;
    float q_l = g_Q[i * DIM + lane];
    float pq0 = g_phiQ[i * RFEAT + lane];
    float pq1 = g_phiQ[i * RFEAT + 32 + lane];
    float acc = 0.f;

    const int* mrow = mask + (size_t)i * N_TOK;
    int mv0 = mrow[lane];
    int mv1 = mrow[32 + lane];

    for (int t = 0; t < N_TOK / TJ; t++) {
        int j0 = t * TJ;
        // stage tiles (256 threads)
        {
            const float4* s = reinterpret_cast<const float4*>(g_Kp + j0 * DIM);
            float4* d = reinterpret_cast<float4*>(sKp);
            #pragma unroll
            for (int u = 0; u < (TJ * DIM / 4) / 256; u++) d[tid + u * 256] = s[tid + u * 256];
            s = reinterpret_cast<const float4*>(g_V + j0 * DIM);
            d = reinterpret_cast<float4*>(sV);
            #pragma unroll
            for (int u = 0; u < (TJ * DIM / 4) / 256; u++) d[tid + u * 256] = s[tid + u * 256];
            s = reinterpret_cast<const float4*>(g_phiK + j0 * RFEAT);
            d = reinterpret_cast<float4*>(sPK);
            #pragma unroll
            for (int u = 0; u < (TJ * RFEAT / 4) / 256; u++) d[tid + u * 256] = s[tid + u * 256];
        }
        __syncthreads();

        unsigned bits0 = __ballot_sync(0xffffffffu, mv0 == 0);
        unsigned bits1 = __ballot_sync(0xffffffffu, mv1 == 0);
        // prefetch next tile's mask (hide DRAM latency under compute)
        if (t + 1 < N_TOK / TJ) {
            mv0 = mrow[j0 + TJ + lane];
            mv1 = mrow[j0 + TJ + 32 + lane];
        }

        #pragma unroll 8
        for (int jj = 0; jj < 32; jj++) {
            float kp  = sKp[jj * DIM + lane];
            float pk0 = sPK[jj * RFEAT + lane];
            float pk1 = sPK[jj * RFEAT + 32 + lane];
            float vv  = sV [jj * DIM + lane];
            float e   = fast_ex2(q_l * kp);
            float val = fmaf(-pq0, pk0, e);
            val       = fmaf(-pq1, pk1, val);
            float sc  = warp_sum(val);
            sc        = ((bits0 >> jj) & 1u) ? sc : 0.f;
            acc       = fmaf(sc, vv, acc);
        }
        #pragma unroll 8
        for (int jj = 0; jj < 32; jj++) {
            int j = 32 + jj;
            float kp  = sKp[j * DIM + lane];
            float pk0 = sPK[j * RFEAT + lane];
            float pk1 = sPK[j * RFEAT + 32 + lane];
            float vv  = sV [j * DIM + lane];
            float e   = fast_ex2(q_l * kp);
            float val = fmaf(-pq0, pk0, e);
            val       = fmaf(-pq1, pk1, val);
            float sc  = warp_sum(val);
            sc        = ((bits1 >> jj) & 1u) ? sc : 0.f;
            acc       = fmaf(sc, vv, acc);
        }
        __syncthreads();
    }

    // epilogue: + low-rank, row-normalize, @Wo + bo
    float lr = 0.f;
    #pragma unroll
    for (int r = 0; r < 32; r++)
        lr = fmaf(__shfl_sync(0xffffffffu, pq0, r), sM[r * DIM + lane], lr);
    #pragma unroll
    for (int r = 0; r < 32; r++)
        lr = fmaf(__shfl_sync(0xffffffffu, pq1, r), sM[(r + 32) * DIM + lane], lr);

    float attn = acc + lr;
    float denom = warp_sum(attn);
    denom = fmaxf(denom, 1e-6f);
    float a = attn / denom;

    sA[w][lane] = a;
    __syncwarp();
    float o = sBo[lane];
    #pragma unroll
    for (int c = 0; c < DIM; c++) o = fmaf(sA[w][c], sWo[c * DIM + lane], o);
    g_attn[i * DIM + lane] = o;
}

// ---------------------------------------------------------------------
// K4: residual + LN1 + FFN(relu) + residual + LN2. One warp per row.
// ---------------------------------------------------------------------
__global__ void k4_ffn(const float* __restrict__ Z,
                       const float* __restrict__ W1, const float* __restrict__ b1,
                       const float* __restrict__ W2, const float* __restrict__ b2,
                       const float* __restrict__ g1, const float* __restrict__ be1,
                       const float* __restrict__ g2, const float* __restrict__ be2,
                       float* __restrict__ out)
{
    __shared__ float sW1[DIM * HDIM];   // 16KB
    __shared__ float sW2[HDIM * DIM];   // 16KB
    __shared__ float sb1[HDIM];
    __shared__ float sb2[DIM], sg1[DIM], sbe1[DIM], sg2[DIM], sbe2[DIM];
    __shared__ float sZ1[8][DIM];
    __shared__ float sH[8][HDIM];

    int tid = threadIdx.x, lane = tid & 31, w = tid >> 5;
    for (int idx = tid; idx < DIM * HDIM; idx += 256) { sW1[idx] = W1[idx]; sW2[idx] = W2[idx]; }
    if (tid < HDIM) sb1[tid] = b1[tid];
    if (tid < DIM) {
        sb2[tid] = b2[tid]; sg1[tid] = g1[tid]; sbe1[tid] = be1[tid];
        sg2[tid] = g2[tid]; sbe2[tid] = be2[tid];
    }
    __syncthreads();

    int i = blockIdx.x * 8 + w;

    float x = Z[i * DIM + lane] + g_attn[i * DIM + lane];
    float mu = warp_sum(x) * (1.f / 32.f);
    float dd = x - mu;
    float var = warp_sum(dd * dd) * (1.f / 32.f);
    float z1 = dd * rsqrtf(var + 1e-5f) * sg1[lane] + sbe1[lane];
    sZ1[w][lane] = z1;
    __syncwarp();

    float h[4];
    #pragma unroll
    for (int u = 0; u < 4; u++) h[u] = sb1[lane + u * 32];
    #pragma unroll
    for (int k = 0; k < DIM; k++) {
        float zk = sZ1[w][k];
        #pragma unroll
        for (int u = 0; u < 4; u++) h[u] = fmaf(zk, sW1[k * HDIM + lane + u * 32], h[u]);
    }
    #pragma unroll
    for (int u = 0; u < 4; u++) sH[w][lane + u * 32] = fmaxf(h[u], 0.f);
    __syncwarp();

    float o = sb2[lane];
    #pragma unroll
    for (int j = 0; j < HDIM; j++) o = fmaf(sH[w][j], sW2[j * DIM + lane], o);

    float y = z1 + o;
    mu = warp_sum(y) * (1.f / 32.f);
    dd = y - mu;
    var = warp_sum(dd * dd) * (1.f / 32.f);
    out[i * DIM + lane] = dd * rsqrtf(var + 1e-5f) * sg2[lane] + sbe2[lane];
}

// ---------------------------------------------------------------------
extern "C" void kernel_launch(void* const* d_in, const int* in_sizes, int n_in,
                              void* d_out, int out_size)
{
    const float* Z    = (const float*)d_in[0];
    const int*   mask = (const int*)  d_in[1];
    const float* Wq = (const float*)d_in[2],  *bq = (const float*)d_in[3];
    const float* Wk = (const float*)d_in[4],  *bk = (const float*)d_in[5];
    const float* Wv = (const float*)d_in[6],  *bv = (const float*)d_in[7];
    const float* Wo = (const float*)d_in[8],  *bo = (const float*)d_in[9];
    const float* W1 = (const float*)d_in[10], *b1 = (const float*)d_in[11];
    const float* W2 = (const float*)d_in[12], *b2 = (const float*)d_in[13];
    const float* g1 = (const float*)d_in[14], *be1 = (const float*)d_in[15];
    const float* g2 = (const float*)d_in[16], *be2 = (const float*)d_in[17];
    const float* omega = (const float*)d_in[18];

    k1_proj<<<N_TOK / 256, 256>>>(Z, Wq, bq, Wk, bk, Wv, bv, omega);
    k2_kv<<<RFEAT, 256>>>();
    k3_attn<<<N_TOK / 8, 256>>>(mask, Wo, bo);
    k4_ffn<<<N_TOK / 8, 256>>>(Z, W1, b1, W2, b2, g1, be1, g2, be2, (float*)d_out);
}

// round 3
// speedup vs baseline: 1.4309x; 1.4309x over previous
#include <cuda_runtime.h>
#include <cuda_bf16.h>
#include <cstdint>

#define N_TOK 2048
#define DIM   32
#define RFEAT 64
#define HDIM  128
#define TJ    64

// ---------- scratch (device globals; no allocation allowed) ----------
__device__ __align__(16) float    g_Q[N_TOK * DIM];
__device__ __align__(16) float    g_KpT[DIM * N_TOK];     // transposed, * log2e/sqrt(d)
__device__ __align__(16) float    g_V[N_TOK * DIM];
__device__ __align__(16) float    g_phiQ[N_TOK * RFEAT];
__device__ __align__(16) float    g_phiK[N_TOK * RFEAT];  // fp32, for k2
__device__ __align__(16) unsigned g_PKT2[(RFEAT / 2) * N_TOK]; // bf16x2 (r-pairs), transposed
__device__ __align__(16) float    g_M[RFEAT * DIM];       // phi_K^T @ V
__device__ __align__(16) float    g_attn[N_TOK * DIM];

__device__ __forceinline__ float fast_ex2(float x) {
    float y;
    asm("ex2.approx.ftz.f32 %0, %1;" : "=f"(y) : "f"(x));
    return y;
}

__device__ __forceinline__ float warp_sum(float v) {
    v += __shfl_xor_sync(0xffffffffu, v, 16);
    v += __shfl_xor_sync(0xffffffffu, v, 8);
    v += __shfl_xor_sync(0xffffffffu, v, 4);
    v += __shfl_xor_sync(0xffffffffu, v, 2);
    v += __shfl_xor_sync(0xffffffffu, v, 1);
    return v;
}

// ---------------------------------------------------------------------
// K1: QKV projection + row norms + random features. Thread = row.
// Also emits transposed K (scaled) and transposed bf16x2-packed phiK.
// ---------------------------------------------------------------------
__global__ void k1_proj(const float* __restrict__ Z,
                        const float* __restrict__ Wq, const float* __restrict__ bq,
                        const float* __restrict__ Wk, const float* __restrict__ bk,
                        const float* __restrict__ Wv, const float* __restrict__ bv,
                        const float* __restrict__ omega)
{
    __shared__ float sW[3][DIM * DIM];
    __shared__ float sB[3][DIM];
    __shared__ float sOm[DIM * RFEAT];

    int tid = threadIdx.x;
    for (int idx = tid; idx < DIM * DIM; idx += 128) {
        sW[0][idx] = Wq[idx]; sW[1][idx] = Wk[idx]; sW[2][idx] = Wv[idx];
    }
    for (int idx = tid; idx < DIM * RFEAT; idx += 128) sOm[idx] = omega[idx];
    if (tid < DIM) { sB[0][tid] = bq[tid]; sB[1][tid] = bk[tid]; sB[2][tid] = bv[tid]; }
    __syncthreads();

    int i = blockIdx.x * 128 + tid;

    float z[DIM];
    const float4* z4 = reinterpret_cast<const float4*>(Z + i * DIM);
    #pragma unroll
    for (int k4 = 0; k4 < DIM / 4; k4++) {
        float4 t = z4[k4];
        z[k4 * 4 + 0] = t.x; z[k4 * 4 + 1] = t.y; z[k4 * 4 + 2] = t.z; z[k4 * 4 + 3] = t.w;
    }

    const float L2E    = 1.4426950408889634f;
    const float KSCALE = (float)(1.4426950408889634 / 5.6568542494923806); // log2e/sqrt(32)

    #pragma unroll 1
    for (int p = 0; p < 3; p++) {
        float a[DIM];
        const float* W = sW[p];
        #pragma unroll
        for (int j = 0; j < DIM; j++) {
            float s = sB[p][j];
            #pragma unroll
            for (int k = 0; k < DIM; k++) s = fmaf(z[k], W[k * DIM + j], s);
            a[j] = s;
        }
        if (p == 0) {          // Q: store row fp32
            float4* dst4 = reinterpret_cast<float4*>(g_Q + i * DIM);
            #pragma unroll
            for (int j4 = 0; j4 < DIM / 4; j4++) {
                float4 t; t.x = a[j4*4+0]; t.y = a[j4*4+1]; t.z = a[j4*4+2]; t.w = a[j4*4+3];
                dst4[j4] = t;
            }
        } else if (p == 1) {   // K: store transposed scaled
            #pragma unroll
            for (int k = 0; k < DIM; k++) g_KpT[k * N_TOK + i] = a[k] * KSCALE;
        } else {               // V
            float4* dst4 = reinterpret_cast<float4*>(g_V + i * DIM);
            #pragma unroll
            for (int j4 = 0; j4 < DIM / 4; j4++) {
                float4 t; t.x = a[j4*4+0]; t.y = a[j4*4+1]; t.z = a[j4*4+2]; t.w = a[j4*4+3];
                dst4[j4] = t;
            }
        }
        if (p < 2) {
            float ss = 0.f;
            #pragma unroll
            for (int k = 0; k < DIM; k++) ss = fmaf(a[k], a[k], ss);
            float inv = 1.f / fmaxf(sqrtf(ss), 1e-6f);
            #pragma unroll
            for (int k = 0; k < DIM; k++) a[k] *= inv;

            float ph[RFEAT];
            #pragma unroll 1
            for (int r4 = 0; r4 < RFEAT / 4; r4++) {
                #pragma unroll
                for (int u = 0; u < 4; u++) {
                    int r = r4 * 4 + u;
                    float dr = 0.f;
                    #pragma unroll
                    for (int k = 0; k < DIM; k++) dr = fmaf(a[k], sOm[k * RFEAT + r], dr);
                    ph[r] = fast_ex2(dr * L2E) * 0.125f; // exp(dr)/sqrt(r), r=64
                }
            }
            float4* dst4 = reinterpret_cast<float4*>((p == 0 ? g_phiQ : g_phiK) + i * RFEAT);
            #pragma unroll
            for (int r4 = 0; r4 < RFEAT / 4; r4++) {
                float4 t; t.x = ph[r4*4+0]; t.y = ph[r4*4+1]; t.z = ph[r4*4+2]; t.w = ph[r4*4+3];
                dst4[r4] = t;
            }
            if (p == 1) {      // packed bf16x2 transposed
                #pragma unroll
                for (int r2 = 0; r2 < RFEAT / 2; r2++) {
                    __nv_bfloat162 h2 = __floats2bfloat162_rn(ph[2*r2], ph[2*r2+1]);
                    g_PKT2[r2 * N_TOK + i] = *reinterpret_cast<unsigned*>(&h2);
                }
            }
        }
    }
}

// ---------------------------------------------------------------------
// K2: M = phi_K^T @ V   [64 x 32]. One block per r. (fp32 path)
// ---------------------------------------------------------------------
__global__ void k2_kv()
{
    int r = blockIdx.x;
    int tid = threadIdx.x, lane = tid & 31, w = tid >> 5;

    float acc[DIM];
    #pragma unroll
    for (int c = 0; c < DIM; c++) acc[c] = 0.f;

    for (int n = tid; n < N_TOK; n += 256) {
        float pk = g_phiK[n * RFEAT + r];
        const float4* v4 = reinterpret_cast<const float4*>(g_V + n * DIM);
        #pragma unroll
        for (int c4 = 0; c4 < DIM / 4; c4++) {
            float4 t = v4[c4];
            acc[c4 * 4 + 0] = fmaf(pk, t.x, acc[c4 * 4 + 0]);
            acc[c4 * 4 + 1] = fmaf(pk, t.y, acc[c4 * 4 + 1]);
            acc[c4 * 4 + 2] = fmaf(pk, t.z, acc[c4 * 4 + 2]);
            acc[c4 * 4 + 3] = fmaf(pk, t.w, acc[c4 * 4 + 3]);
        }
    }

    __shared__ float sm[8][DIM];
    float mine = 0.f;
    #pragma unroll
    for (int c = 0; c < DIM; c++) {
        float s = warp_sum(acc[c]);
        if (lane == c) mine = s;
    }
    sm[w][lane] = mine;
    __syncthreads();
    if (tid < DIM) {
        float t = 0.f;
        #pragma unroll
        for (int ww = 0; ww < 8; ww++) t += sm[ww][tid];
        g_M[r * DIM + tid] = t;
    }
}

// ---------------------------------------------------------------------
// K3: main attention. Warp = row i, lane = j in score phase (NO shuffles),
// lane = c in the AV phase. Tiles pre-transposed in gmem.
// ---------------------------------------------------------------------
__global__ void __launch_bounds__(256, 1) k3_attn(const int* __restrict__ mask,
                                                  const float* __restrict__ Wo,
                                                  const float* __restrict__ bo)
{
    __shared__ float    sKT[DIM][TJ];       // 8KB  K^T tile (scaled)
    __shared__ unsigned sPK2[DIM][TJ];      // 8KB  phiK^T bf16x2 (r-pairs)
    __shared__ float    sV[TJ][DIM];        // 8KB
    __shared__ float    sS[8][TJ];          // 2KB  masked scores per warp
    __shared__ float    sM[RFEAT * DIM];    // 8KB
    __shared__ float    sWo[DIM * DIM];     // 4KB
    __shared__ float    sBo[DIM];
    __shared__ float    sA[8][DIM];

    int tid = threadIdx.x, lane = tid & 31, w = tid >> 5;

    for (int idx = tid; idx < RFEAT * DIM; idx += 256) sM[idx] = g_M[idx];
    for (int idx = tid; idx < DIM * DIM; idx += 256) sWo[idx] = Wo[idx];
    if (tid < DIM) sBo[tid] = bo[tid];

    int i = blockIdx.x * 8 + w;

    float q[DIM], pq[RFEAT];
    #pragma unroll
    for (int k = 0; k < DIM; k++) q[k] = g_Q[i * DIM + k];
    #pragma unroll
    for (int r = 0; r < RFEAT; r++) pq[r] = g_phiQ[i * RFEAT + r];

    const int* mrow = mask + (size_t)i * N_TOK;
    int mvA = mrow[lane], mvB = mrow[32 + lane];
    float acc = 0.f;

    for (int t = 0; t < N_TOK / TJ; t++) {
        int j0 = t * TJ;
        // ---- stage tiles: pure coalesced float4 copies ----
        #pragma unroll
        for (int u = 0; u < 2; u++) {
            int e = tid + u * 256;
            int rk = e >> 4, c4 = e & 15;
            reinterpret_cast<float4*>(&sKT[rk][0])[c4] =
                reinterpret_cast<const float4*>(g_KpT + rk * N_TOK + j0)[c4];
            reinterpret_cast<uint4*>(&sPK2[rk][0])[c4] =
                reinterpret_cast<const uint4*>(g_PKT2 + rk * N_TOK + j0)[c4];
            int rv = e >> 3, cv = e & 7;
            reinterpret_cast<float4*>(&sV[rv][0])[cv] =
                reinterpret_cast<const float4*>(g_V + (j0 + rv) * DIM)[cv];
        }
        __syncthreads();

        int nA = 0, nB = 0;
        if (t + 1 < N_TOK / TJ) {   // prefetch next mask chunk
            nA = mrow[j0 + TJ + lane];
            nB = mrow[j0 + TJ + 32 + lane];
        }

        // ---- half A: j = j0 + lane ----
        {
            float s0 = 0.f, s1 = 0.f, s2 = 0.f, s3 = 0.f;
            #pragma unroll
            for (int k = 0; k < DIM; k += 4) {
                s0 += fast_ex2(q[k + 0] * sKT[k + 0][lane]);
                s1 += fast_ex2(q[k + 1] * sKT[k + 1][lane]);
                s2 += fast_ex2(q[k + 2] * sKT[k + 2][lane]);
                s3 += fast_ex2(q[k + 3] * sKT[k + 3][lane]);
            }
            float p0 = 0.f, p1 = 0.f;
            #pragma unroll
            for (int r2 = 0; r2 < RFEAT / 2; r2++) {
                unsigned pk = sPK2[r2][lane];
                float lo = __uint_as_float(pk << 16);
                float hi = __uint_as_float(pk & 0xffff0000u);
                p0 = fmaf(pq[2 * r2],     lo, p0);
                p1 = fmaf(pq[2 * r2 + 1], hi, p1);
            }
            float val = (s0 + s1) + (s2 + s3) - (p0 + p1);
            sS[w][lane] = (mvA == 0) ? val : 0.f;
        }
        // ---- half B: j = j0 + 32 + lane ----
        {
            float s0 = 0.f, s1 = 0.f, s2 = 0.f, s3 = 0.f;
            #pragma unroll
            for (int k = 0; k < DIM; k += 4) {
                s0 += fast_ex2(q[k + 0] * sKT[k + 0][32 + lane]);
                s1 += fast_ex2(q[k + 1] * sKT[k + 1][32 + lane]);
                s2 += fast_ex2(q[k + 2] * sKT[k + 2][32 + lane]);
                s3 += fast_ex2(q[k + 3] * sKT[k + 3][32 + lane]);
            }
            float p0 = 0.f, p1 = 0.f;
            #pragma unroll
            for (int r2 = 0; r2 < RFEAT / 2; r2++) {
                unsigned pk = sPK2[r2][32 + lane];
                float lo = __uint_as_float(pk << 16);
                float hi = __uint_as_float(pk & 0xffff0000u);
                p0 = fmaf(pq[2 * r2],     lo, p0);
                p1 = fmaf(pq[2 * r2 + 1], hi, p1);
            }
            float val = (s0 + s1) + (s2 + s3) - (p0 + p1);
            sS[w][32 + lane] = (mvB == 0) ? val : 0.f;
        }
        __syncwarp();

        // ---- AV: lane = output column c ----
        #pragma unroll
        for (int jj = 0; jj < TJ; jj += 4) {
            float4 ss = *reinterpret_cast<const float4*>(&sS[w][jj]);
            acc = fmaf(ss.x, sV[jj + 0][lane], acc);
            acc = fmaf(ss.y, sV[jj + 1][lane], acc);
            acc = fmaf(ss.z, sV[jj + 2][lane], acc);
            acc = fmaf(ss.w, sV[jj + 3][lane], acc);
        }
        mvA = nA; mvB = nB;
        __syncthreads();
    }

    // ---- epilogue: + low-rank, row-normalize, @Wo + bo ----
    float lr = 0.f;
    #pragma unroll
    for (int r = 0; r < RFEAT; r++) lr = fmaf(pq[r], sM[r * DIM + lane], lr);

    float attn = acc + lr;
    float denom = fmaxf(warp_sum(attn), 1e-6f);
    float a = attn / denom;

    sA[w][lane] = a;
    __syncwarp();
    float o = sBo[lane];
    #pragma unroll
    for (int c = 0; c < DIM; c++) o = fmaf(sA[w][c], sWo[c * DIM + lane], o);
    g_attn[i * DIM + lane] = o;
}

// ---------------------------------------------------------------------
// K4: residual + LN1 + FFN(relu) + residual + LN2. 32 rows/block to
// amortize weight staging.
// ---------------------------------------------------------------------
__global__ void k4_ffn(const float* __restrict__ Z,
                       const float* __restrict__ W1, const float* __restrict__ b1,
                       const float* __restrict__ W2, const float* __restrict__ b2,
                       const float* __restrict__ g1, const float* __restrict__ be1,
                       const float* __restrict__ g2, const float* __restrict__ be2,
                       float* __restrict__ out)
{
    __shared__ float sW1[DIM * HDIM];
    __shared__ float sW2[HDIM * DIM];
    __shared__ float sb1[HDIM];
    __shared__ float sb2[DIM], sg1[DIM], sbe1[DIM], sg2[DIM], sbe2[DIM];
    __shared__ float sZ1[8][DIM];
    __shared__ float sH[8][HDIM];

    int tid = threadIdx.x, lane = tid & 31, w = tid >> 5;
    for (int idx = tid; idx < DIM * HDIM; idx += 256) { sW1[idx] = W1[idx]; sW2[idx] = W2[idx]; }
    if (tid < HDIM) sb1[tid] = b1[tid];
    if (tid < DIM) {
        sb2[tid] = b2[tid]; sg1[tid] = g1[tid]; sbe1[tid] = be1[tid];
        sg2[tid] = g2[tid]; sbe2[tid] = be2[tid];
    }
    __syncthreads();

    #pragma unroll 1
    for (int tt = 0; tt < 4; tt++) {
        int i = blockIdx.x * 32 + w * 4 + tt;

        float x = Z[i * DIM + lane] + g_attn[i * DIM + lane];
        float mu = warp_sum(x) * (1.f / 32.f);
        float dd = x - mu;
        float var = warp_sum(dd * dd) * (1.f / 32.f);
        float z1 = dd * rsqrtf(var + 1e-5f) * sg1[lane] + sbe1[lane];
        sZ1[w][lane] = z1;
        __syncwarp();

        float h[4];
        #pragma unroll
        for (int u = 0; u < 4; u++) h[u] = sb1[lane + u * 32];
        #pragma unroll
        for (int k = 0; k < DIM; k++) {
            float zk = sZ1[w][k];
            #pragma unroll
            for (int u = 0; u < 4; u++) h[u] = fmaf(zk, sW1[k * HDIM + lane + u * 32], h[u]);
        }
        #pragma unroll
        for (int u = 0; u < 4; u++) sH[w][lane + u * 32] = fmaxf(h[u], 0.f);
        __syncwarp();

        float o = sb2[lane];
        #pragma unroll
        for (int j = 0; j < HDIM; j++) o = fmaf(sH[w][j], sW2[j * DIM + lane], o);

        float y = z1 + o;
        mu = warp_sum(y) * (1.f / 32.f);
        dd = y - mu;
        var = warp_sum(dd * dd) * (1.f / 32.f);
        out[i * DIM + lane] = dd * rsqrtf(var + 1e-5f) * sg2[lane] + sbe2[lane];
        __syncwarp();
    }
}

// ---------------------------------------------------------------------
extern "C" void kernel_launch(void* const* d_in, const int* in_sizes, int n_in,
                              void* d_out, int out_size)
{
    const float* Z    = (const float*)d_in[0];
    const int*   mask = (const int*)  d_in[1];
    const float* Wq = (const float*)d_in[2],  *bq = (const float*)d_in[3];
    const float* Wk = (const float*)d_in[4],  *bk = (const float*)d_in[5];
    const float* Wv = (const float*)d_in[6],  *bv = (const float*)d_in[7];
    const float* Wo = (const float*)d_in[8],  *bo = (const float*)d_in[9];
    const float* W1 = (const float*)d_in[10], *b1 = (const float*)d_in[11];
    const float* W2 = (const float*)d_in[12], *b2 = (const float*)d_in[13];
    const float* g1 = (const float*)d_in[14], *be1 = (const float*)d_in[15];
    const float* g2 = (const float*)d_in[16], *be2 = (const float*)d_in[17];
    const float* omega = (const float*)d_in[18];

    k1_proj<<<N_TOK / 128, 128>>>(Z, Wq, bq, Wk, bk, Wv, bv, omega);
    k2_kv<<<RFEAT, 256>>>();
    k3_attn<<<N_TOK / 8, 256>>>(mask, Wo, bo);
    k4_ffn<<<N_TOK / 32, 256>>>(Z, W1, b1, W2, b2, g1, be1, g2, be2, (float*)d_out);
}

// round 4
// speedup vs baseline: 2.1307x; 1.4891x over previous
#include <cuda_runtime.h>
#include <cuda_bf16.h>
#include <cstdint>

#define N_TOK 2048
#define DIM   32
#define RFEAT 64
#define HDIM  128
#define TJ    64
#define NTILES (N_TOK / TJ)

// ---------- scratch (device globals; no allocation allowed) ----------
__device__ __align__(16) float    g_Q[N_TOK * DIM];
__device__ __align__(16) float    g_KpT[DIM * N_TOK];          // transposed, * log2e/sqrt(d)
__device__ __align__(16) float    g_V[N_TOK * DIM];
__device__ __align__(16) float    g_phiQ[N_TOK * RFEAT];
__device__ __align__(16) float    g_phiK[N_TOK * RFEAT];       // fp32, for k2
__device__ __align__(16) unsigned g_PKT2[(RFEAT / 2) * N_TOK]; // bf16x2 (r-pairs), transposed
__device__ __align__(16) float    g_M[RFEAT * DIM];            // phi_K^T @ V

__device__ __forceinline__ float fast_ex2(float x) {
    float y;
    asm("ex2.approx.ftz.f32 %0, %1;" : "=f"(y) : "f"(x));
    return y;
}

__device__ __forceinline__ float warp_sum(float v) {
    v += __shfl_xor_sync(0xffffffffu, v, 16);
    v += __shfl_xor_sync(0xffffffffu, v, 8);
    v += __shfl_xor_sync(0xffffffffu, v, 4);
    v += __shfl_xor_sync(0xffffffffu, v, 2);
    v += __shfl_xor_sync(0xffffffffu, v, 1);
    return v;
}

#define CP_ASYNC16(dst_s, src_g) \
    asm volatile("cp.async.cg.shared.global [%0], [%1], 16;" :: "r"(dst_s), "l"(src_g))
#define CP_COMMIT() asm volatile("cp.async.commit_group;")
#define CP_WAIT0()  asm volatile("cp.async.wait_group 0;" ::: "memory")

#define L2E    1.4426950408889634f
#define KSCALE ((float)(1.4426950408889634 / 5.6568542494923806)) // log2e/sqrt(32)

// ---------------------------------------------------------------------
// K1: warp-per-row QKV projection + row norms + random features.
// 2048 warps total. Lane = output index.
// ---------------------------------------------------------------------
__global__ void __launch_bounds__(512) k1_proj(const float* __restrict__ Z,
                        const float* __restrict__ Wq, const float* __restrict__ bq,
                        const float* __restrict__ Wk, const float* __restrict__ bk,
                        const float* __restrict__ Wv, const float* __restrict__ bv,
                        const float* __restrict__ omega)
{
    __shared__ float sW[3][DIM * DIM];
    __shared__ float sB[3][DIM];
    __shared__ float sOm[DIM * RFEAT];
    __shared__ float sRow[16][DIM];
    __shared__ float sAn[16][DIM];

    int tid = threadIdx.x, lane = tid & 31, w = tid >> 5;
    for (int idx = tid; idx < DIM * DIM; idx += 512) {
        sW[0][idx] = Wq[idx]; sW[1][idx] = Wk[idx]; sW[2][idx] = Wv[idx];
    }
    for (int idx = tid; idx < DIM * RFEAT; idx += 512) sOm[idx] = omega[idx];
    if (tid < DIM) { sB[0][tid] = bq[tid]; sB[1][tid] = bk[tid]; sB[2][tid] = bv[tid]; }

    int i = blockIdx.x * 16 + w;
    float zk = Z[i * DIM + lane];
    __syncthreads();

    sRow[w][lane] = zk;
    __syncwarp();

    float a[3];
    #pragma unroll
    for (int p = 0; p < 3; p++) {
        float s = sB[p][lane];
        #pragma unroll
        for (int k = 0; k < DIM; k++) s = fmaf(sRow[w][k], sW[p][k * DIM + lane], s);
        a[p] = s;
    }
    g_Q[i * DIM + lane] = a[0];
    g_V[i * DIM + lane] = a[2];
    g_KpT[lane * N_TOK + i] = a[1] * KSCALE;

    #pragma unroll
    for (int p = 0; p < 2; p++) {
        float v = a[p];
        float ss = warp_sum(v * v);
        float an = v * (1.f / fmaxf(sqrtf(ss), 1e-6f));
        sAn[w][lane] = an;
        __syncwarp();
        float d0 = 0.f, d1 = 0.f;
        #pragma unroll
        for (int k = 0; k < DIM; k++) {
            float ab = sAn[w][k];
            float2 om = *(const float2*)&sOm[k * RFEAT + 2 * lane];
            d0 = fmaf(ab, om.x, d0);
            d1 = fmaf(ab, om.y, d1);
        }
        float e0 = fast_ex2(d0 * L2E) * 0.125f;  // exp(d)/sqrt(r), r=64
        float e1 = fast_ex2(d1 * L2E) * 0.125f;
        float2 ph; ph.x = e0; ph.y = e1;
        if (p == 0) {
            *(float2*)&g_phiQ[i * RFEAT + 2 * lane] = ph;
        } else {
            *(float2*)&g_phiK[i * RFEAT + 2 * lane] = ph;
            __nv_bfloat162 h2 = __floats2bfloat162_rn(e0, e1);
            g_PKT2[lane * N_TOK + i] = *(unsigned*)&h2;
        }
        __syncwarp();
    }
}

// ---------------------------------------------------------------------
// K2: M = phi_K^T @ V   [64 x 32]. One block per r.
// ---------------------------------------------------------------------
__global__ void k2_kv()
{
    int r = blockIdx.x;
    int tid = threadIdx.x, lane = tid & 31, w = tid >> 5;

    float acc[DIM];
    #pragma unroll
    for (int c = 0; c < DIM; c++) acc[c] = 0.f;

    for (int n = tid; n < N_TOK; n += 256) {
        float pk = g_phiK[n * RFEAT + r];
        const float4* v4 = reinterpret_cast<const float4*>(g_V + n * DIM);
        #pragma unroll
        for (int c4 = 0; c4 < DIM / 4; c4++) {
            float4 t = v4[c4];
            acc[c4 * 4 + 0] = fmaf(pk, t.x, acc[c4 * 4 + 0]);
            acc[c4 * 4 + 1] = fmaf(pk, t.y, acc[c4 * 4 + 1]);
            acc[c4 * 4 + 2] = fmaf(pk, t.z, acc[c4 * 4 + 2]);
            acc[c4 * 4 + 3] = fmaf(pk, t.w, acc[c4 * 4 + 3]);
        }
    }

    __shared__ float sm[8][DIM];
    float mine = 0.f;
    #pragma unroll
    for (int c = 0; c < DIM; c++) {
        float s = warp_sum(acc[c]);
        if (lane == c) mine = s;
    }
    sm[w][lane] = mine;
    __syncthreads();
    if (tid < DIM) {
        float t = 0.f;
        #pragma unroll
        for (int ww = 0; ww < 8; ww++) t += sm[ww][tid];
        g_M[r * DIM + tid] = t;
    }
}

// ---------------------------------------------------------------------
// K3: attention + fused Wo/LN1/FFN/LN2. 512 threads, 16 rows/block,
// grid 128 (one balanced wave). cp.async double-buffered tiles.
// Dynamic smem layout (bytes):
//   0      sKT  [2][32][64] f32
//   16384  sPK2 [2][32][64] u32
//   32768  sV   [2][64][32] f32
//   49152  sS   [16][64]    f32
//   53248  sPQ  [16][64]    f32
//   57344  sM   [64][32]    f32
//   65536  sWo  [32][32]    f32
//   69632  sW1  [32][128]   f32
//   86016  sW2  [128][32]   f32
//   102400 sH   [16][128]   f32
//   110592 sA   [16][32]    f32
//   112640 sZ1  [16][32]    f32
//   114688 sb1  [128]       f32
//   115200 sVec [6][32]     f32  (bo,b2,g1,be1,g2,be2)
//   total 115968
// ---------------------------------------------------------------------
#define K3_SMEM_BYTES 115968

__device__ __forceinline__ void k3_stage_tile(int j0, int b, int tid)
{
    extern __shared__ char sm_raw[];
    float*    sKT  = (float*)(sm_raw);
    unsigned* sPK2 = (unsigned*)(sm_raw + 16384);
    float*    sV   = (float*)(sm_raw + 32768);

    int rowk = tid >> 4, ck = (tid & 15) * 4;
    unsigned d0 = (unsigned)__cvta_generic_to_shared(&sKT[b * 2048 + rowk * TJ + ck]);
    CP_ASYNC16(d0, g_KpT + rowk * N_TOK + j0 + ck);
    unsigned d1 = (unsigned)__cvta_generic_to_shared(&sPK2[b * 2048 + rowk * TJ + ck]);
    CP_ASYNC16(d1, g_PKT2 + rowk * N_TOK + j0 + ck);
    int rowv = tid >> 3, cv = (tid & 7) * 4;
    unsigned d2 = (unsigned)__cvta_generic_to_shared(&sV[b * 2048 + rowv * DIM + cv]);
    CP_ASYNC16(d2, g_V + (j0 + rowv) * DIM + cv);
}

__global__ void __launch_bounds__(512, 1) k3_attn(
    const int* __restrict__ mask,
    const float* __restrict__ Wo, const float* __restrict__ bo,
    const float* __restrict__ Z,
    const float* __restrict__ W1, const float* __restrict__ b1,
    const float* __restrict__ W2, const float* __restrict__ b2,
    const float* __restrict__ g1, const float* __restrict__ be1,
    const float* __restrict__ g2, const float* __restrict__ be2,
    float* __restrict__ out)
{
    extern __shared__ char sm_raw[];
    float*    sKT  = (float*)(sm_raw);
    unsigned* sPK2 = (unsigned*)(sm_raw + 16384);
    float*    sV   = (float*)(sm_raw + 32768);
    float*    sS   = (float*)(sm_raw + 49152);
    float*    sPQ  = (float*)(sm_raw + 53248);
    float*    sM   = (float*)(sm_raw + 57344);
    float*    sWo  = (float*)(sm_raw + 65536);
    float*    sW1  = (float*)(sm_raw + 69632);
    float*    sW2  = (float*)(sm_raw + 86016);
    float*    sH   = (float*)(sm_raw + 102400);
    float*    sA   = (float*)(sm_raw + 110592);
    float*    sZ1  = (float*)(sm_raw + 112640);
    float*    sb1  = (float*)(sm_raw + 114688);
    float*    sVec = (float*)(sm_raw + 115200);

    int tid = threadIdx.x, lane = tid & 31, w = tid >> 5;

    // stage constants
    for (int idx = tid; idx < RFEAT * DIM; idx += 512) sM[idx] = g_M[idx];
    for (int idx = tid; idx < DIM * DIM; idx += 512) sWo[idx] = Wo[idx];
    for (int idx = tid; idx < DIM * HDIM; idx += 512) { sW1[idx] = W1[idx]; sW2[idx] = W2[idx]; }
    if (tid < HDIM) sb1[tid] = b1[tid];
    if (tid < DIM) {
        sVec[tid] = bo[tid];        sVec[32 + tid] = b2[tid];
        sVec[64 + tid] = g1[tid];   sVec[96 + tid] = be1[tid];
        sVec[128 + tid] = g2[tid];  sVec[160 + tid] = be2[tid];
    }

    int i = blockIdx.x * 16 + w;

    float q[DIM];
    #pragma unroll
    for (int k4 = 0; k4 < DIM / 4; k4++) {
        float4 t = *(const float4*)(g_Q + i * DIM + k4 * 4);
        q[k4 * 4 + 0] = t.x; q[k4 * 4 + 1] = t.y; q[k4 * 4 + 2] = t.z; q[k4 * 4 + 3] = t.w;
    }
    *(float2*)&sPQ[w * RFEAT + 2 * lane] = *(const float2*)(g_phiQ + i * RFEAT + 2 * lane);
    float zres = Z[i * DIM + lane];

    const int* mrow = mask + (size_t)i * N_TOK;
    int mvA = mrow[lane], mvB = mrow[32 + lane];
    float acc = 0.f;

    // prologue: stage tile 0
    k3_stage_tile(0, 0, tid);
    CP_COMMIT();

    for (int t = 0; t < NTILES; t++) {
        CP_WAIT0();
        __syncthreads();
        if (t + 1 < NTILES) { k3_stage_tile((t + 1) * TJ, (t + 1) & 1, tid); CP_COMMIT(); }

        int b = t & 1;
        const float*    KT = sKT + b * 2048;
        const unsigned* PK = sPK2 + b * 2048;
        const float*    Vt = sV + b * 2048;

        int nA = 0, nB = 0;
        if (t + 1 < NTILES) {
            nA = mrow[(t + 1) * TJ + lane];
            nB = mrow[(t + 1) * TJ + 32 + lane];
        }

        // ---- half A: j = t*TJ + lane ----
        {
            float s0 = 0.f, s1 = 0.f, s2 = 0.f, s3 = 0.f;
            #pragma unroll
            for (int k = 0; k < DIM; k += 4) {
                s0 += fast_ex2(q[k + 0] * KT[(k + 0) * TJ + lane]);
                s1 += fast_ex2(q[k + 1] * KT[(k + 1) * TJ + lane]);
                s2 += fast_ex2(q[k + 2] * KT[(k + 2) * TJ + lane]);
                s3 += fast_ex2(q[k + 3] * KT[(k + 3) * TJ + lane]);
            }
            float p0 = 0.f, p1 = 0.f;
            #pragma unroll
            for (int r2 = 0; r2 < RFEAT / 2; r2++) {
                unsigned pk = PK[r2 * TJ + lane];
                float2 pq2 = *(const float2*)&sPQ[w * RFEAT + 2 * r2];
                p0 = fmaf(pq2.x, __uint_as_float(pk << 16), p0);
                p1 = fmaf(pq2.y, __uint_as_float(pk & 0xffff0000u), p1);
            }
            float val = (s0 + s1) + (s2 + s3) - (p0 + p1);
            sS[w * TJ + lane] = (mvA == 0) ? val : 0.f;
        }
        // ---- half B: j = t*TJ + 32 + lane ----
        {
            float s0 = 0.f, s1 = 0.f, s2 = 0.f, s3 = 0.f;
            #pragma unroll
            for (int k = 0; k < DIM; k += 4) {
                s0 += fast_ex2(q[k + 0] * KT[(k + 0) * TJ + 32 + lane]);
                s1 += fast_ex2(q[k + 1] * KT[(k + 1) * TJ + 32 + lane]);
                s2 += fast_ex2(q[k + 2] * KT[(k + 2) * TJ + 32 + lane]);
                s3 += fast_ex2(q[k + 3] * KT[(k + 3) * TJ + 32 + lane]);
            }
            float p0 = 0.f, p1 = 0.f;
            #pragma unroll
            for (int r2 = 0; r2 < RFEAT / 2; r2++) {
                unsigned pk = PK[r2 * TJ + 32 + lane];
                float2 pq2 = *(const float2*)&sPQ[w * RFEAT + 2 * r2];
                p0 = fmaf(pq2.x, __uint_as_float(pk << 16), p0);
                p1 = fmaf(pq2.y, __uint_as_float(pk & 0xffff0000u), p1);
            }
            float val = (s0 + s1) + (s2 + s3) - (p0 + p1);
            sS[w * TJ + 32 + lane] = (mvB == 0) ? val : 0.f;
        }
        __syncwarp();

        // ---- AV: lane = output column c ----
        #pragma unroll
        for (int jj = 0; jj < TJ; jj += 4) {
            float4 ss = *(const float4*)&sS[w * TJ + jj];
            acc = fmaf(ss.x, Vt[(jj + 0) * DIM + lane], acc);
            acc = fmaf(ss.y, Vt[(jj + 1) * DIM + lane], acc);
            acc = fmaf(ss.z, Vt[(jj + 2) * DIM + lane], acc);
            acc = fmaf(ss.w, Vt[(jj + 3) * DIM + lane], acc);
        }
        mvA = nA; mvB = nB;
        __syncwarp();
    }

    // ---- epilogue: + low-rank, normalize, @Wo+bo, LN1, FFN, LN2 ----
    float lr = 0.f;
    #pragma unroll
    for (int r = 0; r < RFEAT; r++) lr = fmaf(sPQ[w * RFEAT + r], sM[r * DIM + lane], lr);

    float attn = acc + lr;
    float denom = fmaxf(warp_sum(attn), 1e-6f);
    float a = attn / denom;

    sA[w * DIM + lane] = a;
    __syncwarp();
    float o = sVec[lane];   // bo
    #pragma unroll
    for (int c = 0; c < DIM; c++) o = fmaf(sA[w * DIM + c], sWo[c * DIM + lane], o);

    // LN1
    float x = zres + o;
    float mu = warp_sum(x) * (1.f / 32.f);
    float dd = x - mu;
    float var = warp_sum(dd * dd) * (1.f / 32.f);
    float z1 = dd * rsqrtf(var + 1e-5f) * sVec[64 + lane] + sVec[96 + lane];
    sZ1[w * DIM + lane] = z1;
    __syncwarp();

    // FFN up + relu
    float h[4];
    #pragma unroll
    for (int u = 0; u < 4; u++) h[u] = sb1[lane + u * 32];
    #pragma unroll
    for (int k = 0; k < DIM; k++) {
        float zk = sZ1[w * DIM + k];
        #pragma unroll
        for (int u = 0; u < 4; u++) h[u] = fmaf(zk, sW1[k * HDIM + lane + u * 32], h[u]);
    }
    #pragma unroll
    for (int u = 0; u < 4; u++) sH[w * HDIM + lane + u * 32] = fmaxf(h[u], 0.f);
    __syncwarp();

    // FFN down (4 accumulators to break the chain)
    float o0 = sVec[32 + lane], o1 = 0.f, o2 = 0.f, o3 = 0.f;
    #pragma unroll
    for (int j = 0; j < HDIM; j += 4) {
        o0 = fmaf(sH[w * HDIM + j + 0], sW2[(j + 0) * DIM + lane], o0);
        o1 = fmaf(sH[w * HDIM + j + 1], sW2[(j + 1) * DIM + lane], o1);
        o2 = fmaf(sH[w * HDIM + j + 2], sW2[(j + 2) * DIM + lane], o2);
        o3 = fmaf(sH[w * HDIM + j + 3], sW2[(j + 3) * DIM + lane], o3);
    }
    float y = z1 + ((o0 + o1) + (o2 + o3));

    // LN2
    float mu2 = warp_sum(y) * (1.f / 32.f);
    float dd2 = y - mu2;
    float var2 = warp_sum(dd2 * dd2) * (1.f / 32.f);
    out[i * DIM + lane] = dd2 * rsqrtf(var2 + 1e-5f) * sVec[128 + lane] + sVec[160 + lane];
}

// ---------------------------------------------------------------------
extern "C" void kernel_launch(void* const* d_in, const int* in_sizes, int n_in,
                              void* d_out, int out_size)
{
    const float* Z    = (const float*)d_in[0];
    const int*   mask = (const int*)  d_in[1];
    const float* Wq = (const float*)d_in[2],  *bq = (const float*)d_in[3];
    const float* Wk = (const float*)d_in[4],  *bk = (const float*)d_in[5];
    const float* Wv = (const float*)d_in[6],  *bv = (const float*)d_in[7];
    const float* Wo = (const float*)d_in[8],  *bo = (const float*)d_in[9];
    const float* W1 = (const float*)d_in[10], *b1 = (const float*)d_in[11];
    const float* W2 = (const float*)d_in[12], *b2 = (const float*)d_in[13];
    const float* g1 = (const float*)d_in[14], *be1 = (const float*)d_in[15];
    const float* g2 = (const float*)d_in[16], *be2 = (const float*)d_in[17];
    const float* omega = (const float*)d_in[18];

    cudaFuncSetAttribute(k3_attn, cudaFuncAttributeMaxDynamicSharedMemorySize, K3_SMEM_BYTES);

    k1_proj<<<N_TOK / 16, 512>>>(Z, Wq, bq, Wk, bk, Wv, bv, omega);
    k2_kv<<<RFEAT, 256>>>();
    k3_attn<<<N_TOK / 16, 512, K3_SMEM_BYTES>>>(mask, Wo, bo, Z,
                                                W1, b1, W2, b2,
                                                g1, be1, g2, be2, (float*)d_out);
}

// round 5
// speedup vs baseline: 2.6362x; 1.2372x over previous
#include <cuda_runtime.h>
#include <cuda_bf16.h>
#include <cstdint>

#define N_TOK 2048
#define DIM   32
#define RFEAT 64
#define HDIM  128
#define TJ    64
#define NTILES (N_TOK / TJ)

// ---------- scratch (device globals; no allocation allowed) ----------
__device__ __align__(16) float    g_Q[N_TOK * DIM];
__device__ __align__(16) float    g_V[N_TOK * DIM];
__device__ __align__(16) float    g_phiQ[N_TOK * RFEAT];
__device__ __align__(16) float    g_phiK[N_TOK * RFEAT];         // fp32, for k2
__device__ __align__(16) unsigned g_PKT2[(RFEAT / 2) * N_TOK];   // [r2][j] bf16x2 r-pairs
__device__ __align__(16) unsigned g_KT2[DIM * (N_TOK / 2)];      // [k][j2] bf16x2 j-pairs (scaled K)
__device__ __align__(16) unsigned g_VT2[DIM * (N_TOK / 2)];      // [c][j2] bf16x2 j-pairs
__device__ __align__(16) float    g_M[RFEAT * DIM];              // phi_K^T @ V

__device__ __forceinline__ float fast_ex2(float x) {
    float y;
    asm("ex2.approx.ftz.f32 %0, %1;" : "=f"(y) : "f"(x));
    return y;
}
__device__ __forceinline__ float warp_sum(float v) {
    v += __shfl_xor_sync(0xffffffffu, v, 16);
    v += __shfl_xor_sync(0xffffffffu, v, 8);
    v += __shfl_xor_sync(0xffffffffu, v, 4);
    v += __shfl_xor_sync(0xffffffffu, v, 2);
    v += __shfl_xor_sync(0xffffffffu, v, 1);
    return v;
}
__device__ __forceinline__ __nv_bfloat162 u2bf(unsigned u) {
    return *reinterpret_cast<__nv_bfloat162*>(&u);
}
__device__ __forceinline__ unsigned packbf(float a, float b) {
    __nv_bfloat162 h = __floats2bfloat162_rn(a, b);
    return *reinterpret_cast<unsigned*>(&h);
}
#define BFLO(u) __uint_as_float((u) << 16)
#define BFHI(u) __uint_as_float((u) & 0xffff0000u)

#define CP_ASYNC16(dst_s, src_g) \
    asm volatile("cp.async.cg.shared.global [%0], [%1], 16;" :: "r"(dst_s), "l"(src_g))
#define CP_COMMIT() asm volatile("cp.async.commit_group;")
#define CP_WAIT0()  asm volatile("cp.async.wait_group 0;" ::: "memory")

#define L2E    1.4426950408889634f
#define KSCALE ((float)(1.4426950408889634 / 5.6568542494923806)) // log2e/sqrt(32)

// ---------------------------------------------------------------------
// K1: warp-per-row QKV + norms + random features; packs transposed
// bf16x2 operands for k3 via an in-block pack phase.
// ---------------------------------------------------------------------
__global__ void __launch_bounds__(512) k1_proj(const float* __restrict__ Z,
                        const float* __restrict__ Wq, const float* __restrict__ bq,
                        const float* __restrict__ Wk, const float* __restrict__ bk,
                        const float* __restrict__ Wv, const float* __restrict__ bv,
                        const float* __restrict__ omega)
{
    __shared__ float sW[3][DIM * DIM];
    __shared__ float sB[3][DIM];
    __shared__ float sOm[DIM * RFEAT];
    __shared__ float sRow[16][DIM];
    __shared__ float sAn[16][DIM];
    __shared__ float sK[16][33];
    __shared__ float sVv[16][33];

    int tid = threadIdx.x, lane = tid & 31, w = tid >> 5;
    for (int idx = tid; idx < DIM * DIM; idx += 512) {
        sW[0][idx] = Wq[idx]; sW[1][idx] = Wk[idx]; sW[2][idx] = Wv[idx];
    }
    for (int idx = tid; idx < DIM * RFEAT; idx += 512) sOm[idx] = omega[idx];
    if (tid < DIM) { sB[0][tid] = bq[tid]; sB[1][tid] = bk[tid]; sB[2][tid] = bv[tid]; }

    int i0 = blockIdx.x * 16;
    int i = i0 + w;
    float zk = Z[i * DIM + lane];
    __syncthreads();

    sRow[w][lane] = zk;
    __syncwarp();

    float a[3];
    #pragma unroll
    for (int p = 0; p < 3; p++) {
        float s0 = sB[p][lane], s1 = 0.f;
        #pragma unroll
        for (int k = 0; k < DIM; k += 2) {
            s0 = fmaf(sRow[w][k],     sW[p][k * DIM + lane],       s0);
            s1 = fmaf(sRow[w][k + 1], sW[p][(k + 1) * DIM + lane], s1);
        }
        a[p] = s0 + s1;
    }
    g_Q[i * DIM + lane] = a[0];
    g_V[i * DIM + lane] = a[2];
    sK[w][lane]  = a[1] * KSCALE;
    sVv[w][lane] = a[2];

    #pragma unroll
    for (int p = 0; p < 2; p++) {
        float v = a[p];
        float ss = warp_sum(v * v);
        float an = v * (1.f / fmaxf(sqrtf(ss), 1e-6f));
        sAn[w][lane] = an;
        __syncwarp();
        float d0 = 0.f, d1 = 0.f, d2 = 0.f, d3 = 0.f;
        #pragma unroll
        for (int k = 0; k < DIM; k += 2) {
            float ab0 = sAn[w][k], ab1 = sAn[w][k + 1];
            float2 om0 = *(const float2*)&sOm[k * RFEAT + 2 * lane];
            float2 om1 = *(const float2*)&sOm[(k + 1) * RFEAT + 2 * lane];
            d0 = fmaf(ab0, om0.x, d0); d1 = fmaf(ab0, om0.y, d1);
            d2 = fmaf(ab1, om1.x, d2); d3 = fmaf(ab1, om1.y, d3);
        }
        float e0 = fast_ex2((d0 + d2) * L2E) * 0.125f;  // exp(d)/sqrt(r), r=64
        float e1 = fast_ex2((d1 + d3) * L2E) * 0.125f;
        float2 ph; ph.x = e0; ph.y = e1;
        if (p == 0) {
            *(float2*)&g_phiQ[i * RFEAT + 2 * lane] = ph;
        } else {
            *(float2*)&g_phiK[i * RFEAT + 2 * lane] = ph;
            g_PKT2[lane * N_TOK + i] = packbf(e0, e1);   // [r2=lane][j=i]
        }
        __syncwarp();
    }

    __syncthreads();
    // pack phase: 256 threads write KT2/VT2 j-pairs for this block's 16 rows
    if (tid < 256) {
        int k = tid >> 3, p = tid & 7;
        int dst = k * (N_TOK / 2) + (i0 >> 1) + p;
        g_KT2[dst] = packbf(sK[2 * p][k],  sK[2 * p + 1][k]);
        g_VT2[dst] = packbf(sVv[2 * p][k], sVv[2 * p + 1][k]);
    }
}

// ---------------------------------------------------------------------
// K2: M = phi_K^T @ V   [64 x 32]. One block per r.
// ---------------------------------------------------------------------
__global__ void k2_kv()
{
    int r = blockIdx.x;
    int tid = threadIdx.x, lane = tid & 31, w = tid >> 5;

    float acc[DIM];
    #pragma unroll
    for (int c = 0; c < DIM; c++) acc[c] = 0.f;

    for (int n = tid; n < N_TOK; n += 256) {
        float pk = g_phiK[n * RFEAT + r];
        const float4* v4 = reinterpret_cast<const float4*>(g_V + n * DIM);
        #pragma unroll
        for (int c4 = 0; c4 < DIM / 4; c4++) {
            float4 t = v4[c4];
            acc[c4 * 4 + 0] = fmaf(pk, t.x, acc[c4 * 4 + 0]);
            acc[c4 * 4 + 1] = fmaf(pk, t.y, acc[c4 * 4 + 1]);
            acc[c4 * 4 + 2] = fmaf(pk, t.z, acc[c4 * 4 + 2]);
            acc[c4 * 4 + 3] = fmaf(pk, t.w, acc[c4 * 4 + 3]);
        }
    }

    __shared__ float sm[8][DIM];
    float mine = 0.f;
    #pragma unroll
    for (int c = 0; c < DIM; c++) {
        float s = warp_sum(acc[c]);
        if (lane == c) mine = s;
    }
    sm[w][lane] = mine;
    __syncthreads();
    if (tid < DIM) {
        float t = 0.f;
        #pragma unroll
        for (int ww = 0; ww < 8; ww++) t += sm[ww][tid];
        g_M[r * DIM + tid] = t;
    }
}

// ---------------------------------------------------------------------
// K3: attention + fused Wo/LN1/FFN/LN2. 512 threads, 16 rows/block.
// Thread owns j-pair (2lane, 2lane+1); bf16x2 KT/PK/VT tiles.
// Dynamic smem layout (byte offsets):
//   0      sKT2 [2][32][32]  u32   8192
//   8192   sPK2 [2][32][64]  u32  16384
//   24576  sVT2 [2][32][36]  u32   9216 (stride-36 padded)
//   33792  sS   [16][64]     f32   4096
//   37888  sPQ  [16][64]     f32   4096
//   41984  sM   [64][32]     f32   8192
//   50176  sWo  [32][32]     f32   4096
//   54272  sW1  [32][128]    f32  16384
//   70656  sW2  [128][32]    f32  16384
//   87040  sH   [16][128]    f32   8192
//   95232  sA   [16][32]     f32   2048
//   97280  sZ1  [16][32]     f32   2048
//   99328  sb1  [128]        f32    512
//   99840  sVec [6][32]      f32    768
//   total 100608
// ---------------------------------------------------------------------
#define K3_SMEM_BYTES 100608

__device__ __forceinline__ void k3_stage_tile(int t, int b, int tid, unsigned smem_base)
{
    if (tid < 256) {
        int k = tid >> 3, c = tid & 7;
        unsigned d = smem_base + (unsigned)(b * 4096 + k * 128 + c * 16);
        CP_ASYNC16(d, g_KT2 + k * (N_TOK / 2) + t * 32 + c * 4);
    } else {
        int idx = tid - 256;
        int cc = idx >> 3, c = idx & 7;
        unsigned d = smem_base + (unsigned)(24576 + b * 4608 + cc * 144 + c * 16);
        CP_ASYNC16(d, g_VT2 + cc * (N_TOK / 2) + t * 32 + c * 4);
    }
    int r2 = tid >> 4, c2 = tid & 15;
    unsigned d = smem_base + (unsigned)(8192 + b * 8192 + r2 * 256 + c2 * 16);
    CP_ASYNC16(d, g_PKT2 + r2 * N_TOK + t * 64 + c2 * 4);
}

__global__ void __launch_bounds__(512, 1) k3_attn(
    const int* __restrict__ mask,
    const float* __restrict__ Wo, const float* __restrict__ bo,
    const float* __restrict__ Z,
    const float* __restrict__ W1, const float* __restrict__ b1,
    const float* __restrict__ W2, const float* __restrict__ b2,
    const float* __restrict__ g1, const float* __restrict__ be1,
    const float* __restrict__ g2, const float* __restrict__ be2,
    float* __restrict__ out)
{
    extern __shared__ char sm_raw[];
    unsigned smem_base = (unsigned)__cvta_generic_to_shared(sm_raw);
    unsigned* sKT2u = (unsigned*)(sm_raw);
    unsigned* sPK2u = (unsigned*)(sm_raw + 8192);
    unsigned* sVT2u = (unsigned*)(sm_raw + 24576);
    float*    sS    = (float*)(sm_raw + 33792);
    float*    sPQ   = (float*)(sm_raw + 37888);
    float*    sM    = (float*)(sm_raw + 41984);
    float*    sWo   = (float*)(sm_raw + 50176);
    float*    sW1   = (float*)(sm_raw + 54272);
    float*    sW2   = (float*)(sm_raw + 70656);
    float*    sH    = (float*)(sm_raw + 87040);
    float*    sA    = (float*)(sm_raw + 95232);
    float*    sZ1   = (float*)(sm_raw + 97280);
    float*    sb1   = (float*)(sm_raw + 99328);
    float*    sVec  = (float*)(sm_raw + 99840);

    int tid = threadIdx.x, lane = tid & 31, w = tid >> 5;

    // stage constants
    for (int idx = tid; idx < RFEAT * DIM; idx += 512) sM[idx] = g_M[idx];
    for (int idx = tid; idx < DIM * DIM; idx += 512) sWo[idx] = Wo[idx];
    for (int idx = tid; idx < DIM * HDIM; idx += 512) { sW1[idx] = W1[idx]; sW2[idx] = W2[idx]; }
    if (tid < HDIM) sb1[tid] = b1[tid];
    if (tid < DIM) {
        sVec[tid] = bo[tid];        sVec[32 + tid] = b2[tid];
        sVec[64 + tid] = g1[tid];   sVec[96 + tid] = be1[tid];
        sVec[128 + tid] = g2[tid];  sVec[160 + tid] = be2[tid];
    }

    int i = blockIdx.x * 16 + w;

    float q[DIM];
    #pragma unroll
    for (int k4 = 0; k4 < DIM / 4; k4++) {
        float4 t = *(const float4*)(g_Q + i * DIM + k4 * 4);
        q[k4 * 4 + 0] = t.x; q[k4 * 4 + 1] = t.y; q[k4 * 4 + 2] = t.z; q[k4 * 4 + 3] = t.w;
    }
    unsigned pq2[RFEAT / 2];
    #pragma unroll
    for (int r4 = 0; r4 < RFEAT / 4; r4++) {
        float4 t = *(const float4*)(g_phiQ + i * RFEAT + r4 * 4);
        pq2[2 * r4]     = packbf(t.x, t.y);
        pq2[2 * r4 + 1] = packbf(t.z, t.w);
    }
    *(float2*)&sPQ[w * RFEAT + 2 * lane] = *(const float2*)(g_phiQ + i * RFEAT + 2 * lane);
    float zres = Z[i * DIM + lane];

    const int2* mrow2 = (const int2*)(mask + (size_t)i * N_TOK);
    int2 mv = mrow2[lane];
    float acc0 = 0.f, acc1 = 0.f;

    k3_stage_tile(0, 0, tid, smem_base);
    CP_COMMIT();

    for (int t = 0; t < NTILES; t++) {
        CP_WAIT0();
        __syncthreads();
        if (t + 1 < NTILES) { k3_stage_tile(t + 1, (t + 1) & 1, tid, smem_base); CP_COMMIT(); }

        int b = t & 1;
        const unsigned* KT = sKT2u + b * 1024;
        const uint2*    PK = (const uint2*)(sPK2u + b * 2048);
        const unsigned* VT = sVT2u + b * 1152 + lane * 36;

        int2 nmv = make_int2(0, 0);
        if (t + 1 < NTILES) nmv = mrow2[(t + 1) * 32 + lane];

        // ---- exp part: j-pair per thread ----
        float eA0 = 0.f, eA1 = 0.f, eB0 = 0.f, eB1 = 0.f;
        #pragma unroll
        for (int k = 0; k < DIM; k += 2) {
            unsigned u0 = KT[k * 32 + lane];
            unsigned u1 = KT[(k + 1) * 32 + lane];
            eA0 += fast_ex2(q[k]     * BFLO(u0));
            eB0 += fast_ex2(q[k]     * BFHI(u0));
            eA1 += fast_ex2(q[k + 1] * BFLO(u1));
            eB1 += fast_ex2(q[k + 1] * BFHI(u1));
        }

        // ---- phi part: HFMA2, 2 split accumulators per j ----
        __nv_bfloat162 pA0 = __floats2bfloat162_rn(0.f, 0.f);
        __nv_bfloat162 pA1 = pA0, pB0 = pA0, pB1 = pA0;
        #pragma unroll
        for (int r2 = 0; r2 < RFEAT / 2; r2 += 2) {
            uint2 k0 = PK[r2 * 32 + lane];
            uint2 k1 = PK[(r2 + 1) * 32 + lane];
            pA0 = __hfma2(u2bf(pq2[r2]),     u2bf(k0.x), pA0);
            pB0 = __hfma2(u2bf(pq2[r2]),     u2bf(k0.y), pB0);
            pA1 = __hfma2(u2bf(pq2[r2 + 1]), u2bf(k1.x), pA1);
            pB1 = __hfma2(u2bf(pq2[r2 + 1]), u2bf(k1.y), pB1);
        }
        float2 fa0 = __bfloat1622float2(pA0), fa1 = __bfloat1622float2(pA1);
        float2 fb0 = __bfloat1622float2(pB0), fb1 = __bfloat1622float2(pB1);
        float phiA = (fa0.x + fa0.y) + (fa1.x + fa1.y);
        float phiB = (fb0.x + fb0.y) + (fb1.x + fb1.y);

        float2 sv;
        sv.x = (mv.x == 0) ? ((eA0 + eA1) - phiA) : 0.f;
        sv.y = (mv.y == 0) ? ((eB0 + eB1) - phiB) : 0.f;
        *(float2*)&sS[w * TJ + 2 * lane] = sv;
        __syncwarp();

        // ---- AV: lane = output column c, V^T bf16x2 tiles ----
        const float4* SS = (const float4*)&sS[w * TJ];
        #pragma unroll
        for (int j8 = 0; j8 < 8; j8++) {
            uint4 v = *(const uint4*)(VT + j8 * 4);
            float4 s0 = SS[2 * j8], s1 = SS[2 * j8 + 1];
            acc0 = fmaf(s0.x, BFLO(v.x), acc0); acc1 = fmaf(s0.y, BFHI(v.x), acc1);
            acc0 = fmaf(s0.z, BFLO(v.y), acc0); acc1 = fmaf(s0.w, BFHI(v.y), acc1);
            acc0 = fmaf(s1.x, BFLO(v.z), acc0); acc1 = fmaf(s1.y, BFHI(v.z), acc1);
            acc0 = fmaf(s1.z, BFLO(v.w), acc0); acc1 = fmaf(s1.w, BFHI(v.w), acc1);
        }
        mv = nmv;
        __syncwarp();
    }

    // ---- epilogue: + low-rank, normalize, @Wo+bo, LN1, FFN, LN2 ----
    float lr = 0.f;
    #pragma unroll
    for (int r = 0; r < RFEAT; r++) lr = fmaf(sPQ[w * RFEAT + r], sM[r * DIM + lane], lr);

    float attn = (acc0 + acc1) + lr;
    float denom = fmaxf(warp_sum(attn), 1e-6f);
    float a = attn / denom;

    sA[w * DIM + lane] = a;
    __syncwarp();
    float o = sVec[lane];   // bo
    #pragma unroll
    for (int c = 0; c < DIM; c++) o = fmaf(sA[w * DIM + c], sWo[c * DIM + lane], o);

    // LN1
    float x = zres + o;
    float mu = warp_sum(x) * (1.f / 32.f);
    float dd = x - mu;
    float var = warp_sum(dd * dd) * (1.f / 32.f);
    float z1 = dd * rsqrtf(var + 1e-5f) * sVec[64 + lane] + sVec[96 + lane];
    sZ1[w * DIM + lane] = z1;
    __syncwarp();

    // FFN up + relu
    float h[4];
    #pragma unroll
    for (int u = 0; u < 4; u++) h[u] = sb1[lane + u * 32];
    #pragma unroll
    for (int k = 0; k < DIM; k++) {
        float zk = sZ1[w * DIM + k];
        #pragma unroll
        for (int u = 0; u < 4; u++) h[u] = fmaf(zk, sW1[k * HDIM + lane + u * 32], h[u]);
    }
    #pragma unroll
    for (int u = 0; u < 4; u++) sH[w * HDIM + lane + u * 32] = fmaxf(h[u], 0.f);
    __syncwarp();

    // FFN down
    float o0 = sVec[32 + lane], o1 = 0.f, o2 = 0.f, o3 = 0.f;
    #pragma unroll
    for (int j = 0; j < HDIM; j += 4) {
        o0 = fmaf(sH[w * HDIM + j + 0], sW2[(j + 0) * DIM + lane], o0);
        o1 = fmaf(sH[w * HDIM + j + 1], sW2[(j + 1) * DIM + lane], o1);
        o2 = fmaf(sH[w * HDIM + j + 2], sW2[(j + 2) * DIM + lane], o2);
        o3 = fmaf(sH[w * HDIM + j + 3], sW2[(j + 3) * DIM + lane], o3);
    }
    float y = z1 + ((o0 + o1) + (o2 + o3));

    // LN2
    float mu2 = warp_sum(y) * (1.f / 32.f);
    float dd2 = y - mu2;
    float var2 = warp_sum(dd2 * dd2) * (1.f / 32.f);
    out[i * DIM + lane] = dd2 * rsqrtf(var2 + 1e-5f) * sVec[128 + lane] + sVec[160 + lane];
}

// ---------------------------------------------------------------------
extern "C" void kernel_launch(void* const* d_in, const int* in_sizes, int n_in,
                              void* d_out, int out_size)
{
    const float* Z    = (const float*)d_in[0];
    const int*   mask = (const int*)  d_in[1];
    const float* Wq = (const float*)d_in[2],  *bq = (const float*)d_in[3];
    const float* Wk = (const float*)d_in[4],  *bk = (const float*)d_in[5];
    const float* Wv = (const float*)d_in[6],  *bv = (const float*)d_in[7];
    const float* Wo = (const float*)d_in[8],  *bo = (const float*)d_in[9];
    const float* W1 = (const float*)d_in[10], *b1 = (const float*)d_in[11];
    const float* W2 = (const float*)d_in[12], *b2 = (const float*)d_in[13];
    const float* g1 = (const float*)d_in[14], *be1 = (const float*)d_in[15];
    const float* g2 = (const float*)d_in[16], *be2 = (const float*)d_in[17];
    const float* omega = (const float*)d_in[18];

    cudaFuncSetAttribute(k3_attn, cudaFuncAttributeMaxDynamicSharedMemorySize, K3_SMEM_BYTES);

    k1_proj<<<N_TOK / 16, 512>>>(Z, Wq, bq, Wk, bk, Wv, bv, omega);
    k2_kv<<<RFEAT, 256>>>();
    k3_attn<<<N_TOK / 16, 512, K3_SMEM_BYTES>>>(mask, Wo, bo, Z,
                                                W1, b1, W2, b2,
                                                g1, be1, g2, be2, (float*)d_out);
}